// round 8
// baseline (speedup 1.0000x reference)
#include <cuda_runtime.h>
#include <cstdint>

#define D_MODEL 1024
#define N_EXP   8
#define N_TOK   8192
#define CAP     8192
#define MB_MAX  64            // max 128-row m-blocks per expert
#define BM      128
#define BN      256
#define BK      32
#define KTILES  32
#define STAGE_B 49152         // 16KB A + 32KB B per stage
#define SMEM_T  (3 * STAGE_B) // 144 KB

// ---------------- device scratch (no allocation allowed) ----------------
__device__ int   g_cnt[N_EXP];
__device__ int   g_tok[N_EXP * CAP];
__device__ float g_wgt[N_EXP * CAP];
// permuted+rounded A tiles: [e][mb][kt][4096 floats]  (fragment order)
__device__ float g_A1[(size_t)N_EXP * MB_MAX * KTILES * 4096];
__device__ float g_A2[(size_t)N_EXP * MB_MAX * KTILES * 4096];
// permuted+rounded weights: [e][nb(8)][kt][4096 floats]  (128-col blocks)
__device__ float g_W1p[(size_t)N_EXP * 8 * KTILES * 4096];
__device__ float g_W2p[(size_t)N_EXP * 8 * KTILES * 4096];

// ---------------- helpers ----------------
__device__ __forceinline__ uint32_t smem_u32(const void* p) {
    uint32_t a;
    asm("{ .reg .u64 t; cvta.to.shared.u64 t, %1; cvt.u32.u64 %0, t; }" : "=r"(a) : "l"(p));
    return a;
}
__device__ __forceinline__ unsigned f2tf32(float f) {
    unsigned r; asm("cvt.rna.tf32.f32 %0, %1;" : "=r"(r) : "f"(f)); return r;
}
__device__ __forceinline__ void mma_tf32(float* c, const uint32_t* a, const uint32_t* b) {
    asm volatile(
        "mma.sync.aligned.m16n8k8.row.col.f32.tf32.tf32.f32 "
        "{%0,%1,%2,%3}, {%4,%5,%6,%7}, {%8,%9}, {%0,%1,%2,%3};"
        : "+f"(c[0]), "+f"(c[1]), "+f"(c[2]), "+f"(c[3])
        : "r"(a[0]), "r"(a[1]), "r"(a[2]), "r"(a[3]),
          "r"(b[0]), "r"(b[1]));
}
#define CP_ASYNC16(dst, src) \
    asm volatile("cp.async.cg.shared.global [%0], [%1], 16;" :: "r"(dst), "l"(src))
#define CP_COMMIT()  asm volatile("cp.async.commit_group;" ::: "memory")
#define CP_WAIT1()   asm volatile("cp.async.wait_group 1;" ::: "memory")
#define LDS128(r, a) \
    asm volatile("ld.shared.v4.b32 {%0,%1,%2,%3}, [%4];" \
        : "=r"((r)[0]), "=r"((r)[1]), "=r"((r)[2]), "=r"((r)[3]) : "r"(a))
#define LDS64(r, a) \
    asm volatile("ld.shared.v2.b32 {%0,%1}, [%2];" \
        : "=r"((r)[0]), "=r"((r)[1]) : "r"(a))

// A fragment slot for element (r in 0..127, k in 0..31)
__device__ __forceinline__ int a_fidx(int r, int k) {
    return (((r >> 4) * 4 + (k >> 3)) << 7) + (((r & 7) * 4 + (k & 3)) << 2) +
           ((r >> 3) & 1) + 2 * ((k >> 2) & 1);
}
// B fragment slot for element (n in 0..127, k in 0..31)
__device__ __forceinline__ int b_fidx(int n, int k) {
    return (((n >> 3) * 4 + (k >> 3)) << 6) + (((n & 7) * 4 + (k & 3)) << 1) +
           ((k >> 2) & 1);
}

// ---------------- kernel: reset counters ----------------
__global__ void zero_cnt_kernel() {
    if (threadIdx.x < N_EXP) g_cnt[threadIdx.x] = 0;
}

// ---------------- kernel: gating + top-2 ----------------
__global__ void gate_kernel(const float* __restrict__ x,
                            const float* __restrict__ Wg,
                            const float* __restrict__ bg) {
    int tok  = blockIdx.x * 8 + (threadIdx.x >> 5);
    int lane = threadIdx.x & 31;
    if (tok >= N_TOK) return;
    const float* xr = x + (size_t)tok * D_MODEL;

    float s[8];
#pragma unroll
    for (int e = 0; e < 8; e++) s[e] = 0.f;
    for (int k = lane; k < D_MODEL; k += 32) {
        float xv = xr[k];
        const float4* wr = (const float4*)(Wg + (size_t)k * N_EXP);
        float4 w0 = wr[0], w1 = wr[1];
        s[0] += xv * w0.x; s[1] += xv * w0.y; s[2] += xv * w0.z; s[3] += xv * w0.w;
        s[4] += xv * w1.x; s[5] += xv * w1.y; s[6] += xv * w1.z; s[7] += xv * w1.w;
    }
#pragma unroll
    for (int e = 0; e < 8; e++)
#pragma unroll
        for (int off = 16; off > 0; off >>= 1)
            s[e] += __shfl_xor_sync(0xffffffffu, s[e], off);

    if (lane == 0) {
        float best = -3.4e38f, best2 = -3.4e38f;
        int e0 = 0, e1 = 0;
#pragma unroll
        for (int e = 0; e < 8; e++) {
            float v = s[e] + bg[e];
            if (v > best)       { best2 = best; e1 = e0; best = v; e0 = e; }
            else if (v > best2) { best2 = v; e1 = e; }
        }
        int p0 = atomicAdd(&g_cnt[e0], 1);
        g_tok[e0 * CAP + p0] = tok;
        g_wgt[e0 * CAP + p0] = best;
        int p1 = atomicAdd(&g_cnt[e1], 1);
        g_tok[e1 * CAP + p1] = tok;
        g_wgt[e1 * CAP + p1] = best2;
    }
}

// ---------------- kernel: weight permute+round ----------------
__global__ void w_perm_kernel(const float* __restrict__ W, int which) {
    __shared__ float stg[4096];
    float* dst = which ? g_W2p : g_W1p;
    const int kt = blockIdx.x, nb = blockIdx.y, e = blockIdx.z;
    const int tid = threadIdx.x;
    const int kr  = tid >> 3;
    const int nc8 = tid & 7;
    const float* Ws = W + (size_t)e * D_MODEL * D_MODEL;
#pragma unroll
    for (int i = 0; i < 4; i++) {
        int n_in = nc8 * 16 + i * 4;
        float4 v = *(const float4*)(Ws + (size_t)(kt * 32 + kr) * D_MODEL + nb * 128 + n_in);
        stg[b_fidx(n_in + 0, kr)] = __uint_as_float(f2tf32(v.x));
        stg[b_fidx(n_in + 1, kr)] = __uint_as_float(f2tf32(v.y));
        stg[b_fidx(n_in + 2, kr)] = __uint_as_float(f2tf32(v.z));
        stg[b_fidx(n_in + 3, kr)] = __uint_as_float(f2tf32(v.w));
    }
    __syncthreads();
    float4* d4 = (float4*)(dst + ((size_t)(e * 8 + nb) * KTILES + kt) * 4096);
    const float4* s4 = (const float4*)stg;
#pragma unroll
    for (int i = 0; i < 4; i++) d4[tid + i * 256] = s4[tid + i * 256];
}

// ---------------- kernel: gather + round + permute X -> g_A1 ----------------
__global__ void a1_perm_kernel(const float* __restrict__ x) {
    __shared__ float stg[4096];
    const int mb = blockIdx.x, e = blockIdx.y;
    const int cnt = g_cnt[e];
    if (mb * BM >= cnt) return;
    const int tid = threadIdx.x;
    const int r    = tid >> 1;
    const int half = tid & 1;
    int ai  = mb * BM + r;
    int tok = (ai < cnt) ? g_tok[e * CAP + ai] : g_tok[e * CAP];
    const float* src = x + (size_t)tok * D_MODEL;
    float* dstb = g_A1 + (size_t)(e * MB_MAX + mb) * KTILES * 4096;

    for (int kt = 0; kt < KTILES; kt++) {
#pragma unroll
        for (int i = 0; i < 4; i++) {
            int k_in = half * 16 + i * 4;
            float4 v = *(const float4*)(src + kt * 32 + k_in);
            stg[a_fidx(r, k_in + 0)] = __uint_as_float(f2tf32(v.x));
            stg[a_fidx(r, k_in + 1)] = __uint_as_float(f2tf32(v.y));
            stg[a_fidx(r, k_in + 2)] = __uint_as_float(f2tf32(v.z));
            stg[a_fidx(r, k_in + 3)] = __uint_as_float(f2tf32(v.w));
        }
        __syncthreads();
        float4* d4 = (float4*)(dstb + (size_t)kt * 4096);
        const float4* s4 = (const float4*)stg;
#pragma unroll
        for (int i = 0; i < 4; i++) d4[tid + i * 256] = s4[tid + i * 256];
        __syncthreads();
    }
}

// ---------------- kernel: grouped GEMM (BM=128, BN=256, warp tile 64x64) ----
// 8 warps (2m x 4n), 3-stage cp.async ring, one barrier per k-tile.
// FIRST: D = relu(A1 @ W1^T + b1) -> g_A2 ; else: out[tok] += w*(A2 @ W2^T + b2)
template <bool FIRST>
__global__ void __launch_bounds__(256)
moe_gemm(const float* __restrict__ bias, float* __restrict__ out) {
    const int e   = blockIdx.z;
    const int cnt = g_cnt[e];
    const int mb  = blockIdx.y;
    if (mb * BM >= cnt) return;
    const int nb2 = blockIdx.x;          // 0..3 (256-col block)

    extern __shared__ __align__(128) char smem[];
    const uint32_t sb = smem_u32(smem);
    const int tid  = threadIdx.x;
    const int lane = tid & 31;
    const int warp = tid >> 5;
    const int wm   = warp >> 2;          // 0..1 (64-row)
    const int wn   = warp & 3;           // 0..3 (64-col)
    const int g    = lane >> 2;
    const int tg   = lane & 3;

    const float* Asrc = (FIRST ? g_A1 : g_A2) + (size_t)(e * MB_MAX + mb) * KTILES * 4096;
    const float* Wp   = FIRST ? g_W1p : g_W2p;
    const float* Bsrc0 = Wp + (size_t)(e * 8 + 2 * nb2)     * KTILES * 4096;
    const float* Bsrc1 = Wp + (size_t)(e * 8 + 2 * nb2 + 1) * KTILES * 4096;

    float c[32][4];
#pragma unroll
    for (int i = 0; i < 32; i++)
#pragma unroll
        for (int j = 0; j < 4; j++) c[i][j] = 0.f;

    // stage layout: [0,16K) A | [16K,32K) B block lo | [32K,48K) B block hi
    auto load_stage = [&](int kt, int s) {
        uint32_t da = sb + s * STAGE_B + tid * 16;
        const float* sa = Asrc  + (size_t)kt * 4096 + tid * 4;
        const float* s0 = Bsrc0 + (size_t)kt * 4096 + tid * 4;
        const float* s1 = Bsrc1 + (size_t)kt * 4096 + tid * 4;
#pragma unroll
        for (int cc = 0; cc < 4; cc++) {
            CP_ASYNC16(da + cc * 4096,         sa + cc * 1024);
            CP_ASYNC16(da + 16384 + cc * 4096, s0 + cc * 1024);
            CP_ASYNC16(da + 32768 + cc * 4096, s1 + cc * 1024);
        }
    };

    load_stage(0, 0); CP_COMMIT();
    load_stage(1, 1); CP_COMMIT();

    const uint32_t aoff = wm * 8192 + lane * 16;
    const uint32_t boff = 16384 + (wn >> 1) * 16384 + (wn & 1) * 8192 + lane * 8;

    for (int it = 0; it < KTILES; it++) {
        CP_WAIT1();
        __syncthreads();
        // stage (it+2)%3 == (it-1)%3: its reads finished before this barrier
        if (it + 2 < KTILES) load_stage(it + 2, (it + 2) % 3);
        CP_COMMIT();

        const uint32_t st = sb + (it % 3) * STAGE_B;
#pragma unroll
        for (int kk = 0; kk < 4; kk++) {
            uint32_t a[4][4], b[8][2];
#pragma unroll
            for (int mi = 0; mi < 4; mi++)
                LDS128(a[mi], st + aoff + mi * 2048 + kk * 512);
#pragma unroll
            for (int ni = 0; ni < 8; ni++)
                LDS64(b[ni], st + boff + ni * 1024 + kk * 256);
#pragma unroll
            for (int mi = 0; mi < 4; mi++)
#pragma unroll
                for (int ni = 0; ni < 8; ni++)
                    mma_tf32(c[mi * 8 + ni], a[mi], b[ni]);
        }
    }

    // ---- epilogue ----
    const float* brow = bias + e * D_MODEL;
#pragma unroll
    for (int mi = 0; mi < 4; mi++) {
#pragma unroll
        for (int ni = 0; ni < 8; ni++) {
#pragma unroll
            for (int j = 0; j < 4; j++) {
                int r_blk = wm * 64 + mi * 16 + g + 8 * (j >> 1);
                int grow  = mb * BM + r_blk;
                if (grow >= cnt) continue;
                int n_glob = nb2 * BN + wn * 64 + ni * 8 + 2 * tg + (j & 1);
                float v = c[mi * 8 + ni][j] + __ldg(brow + n_glob);
                if (FIRST) {
                    v = fmaxf(v, 0.f);
                    int kt = n_glob >> 5, k_in = n_glob & 31;
                    g_A2[((size_t)(e * MB_MAX + mb) * KTILES + kt) * 4096 +
                         a_fidx(r_blk, k_in)] = __uint_as_float(f2tf32(v));
                } else {
                    float w = g_wgt[e * CAP + grow];
                    atomicAdd(out + (size_t)g_tok[e * CAP + grow] * D_MODEL + n_glob,
                              v * w);
                }
            }
        }
    }
}

// ---------------- launch ----------------
extern "C" void kernel_launch(void* const* d_in, const int* in_sizes, int n_in,
                              void* d_out, int out_size) {
    const float* x  = (const float*)d_in[0];
    const float* Wg = (const float*)d_in[1];
    const float* bg = (const float*)d_in[2];
    const float* W1 = (const float*)d_in[3];
    const float* b1 = (const float*)d_in[4];
    const float* W2 = (const float*)d_in[5];
    const float* b2 = (const float*)d_in[6];
    float* out = (float*)d_out;

    cudaFuncSetAttribute(moe_gemm<true>,
                         cudaFuncAttributeMaxDynamicSharedMemorySize, SMEM_T);
    cudaFuncSetAttribute(moe_gemm<false>,
                         cudaFuncAttributeMaxDynamicSharedMemorySize, SMEM_T);

    cudaMemsetAsync(out, 0, (size_t)out_size * sizeof(float));
    zero_cnt_kernel<<<1, 32>>>();
    gate_kernel<<<N_TOK / 8, 256>>>(x, Wg, bg);

    dim3 wg(KTILES, 8, N_EXP);
    w_perm_kernel<<<wg, 256>>>(W1, 0);
    w_perm_kernel<<<wg, 256>>>(W2, 1);
    a1_perm_kernel<<<dim3(MB_MAX, N_EXP), 256>>>(x);

    dim3 grid(D_MODEL / BN, MB_MAX, N_EXP);   // (4, 64, 8)
    moe_gemm<true><<<grid, 256, SMEM_T>>>(b1, nullptr);
    moe_gemm<false><<<grid, 256, SMEM_T>>>(b2, out);
}

// round 9
// speedup vs baseline: 1.1597x; 1.1597x over previous
#include <cuda_runtime.h>
#include <cstdint>

#define D_MODEL 1024
#define N_EXP   8
#define N_TOK   8192
#define CAP     8192
#define MB_MAX  64            // max 128-row m-blocks per expert
#define BM      128
#define BN      128
#define BK      32
#define KTILES  32
#define NTHREADS 128
#define STAGE_B 32768         // 16KB A + 16KB B per stage
#define SMEM_T  (3 * STAGE_B) // 96 KB

// ---------------- device scratch (no allocation allowed) ----------------
__device__ int   g_cnt[N_EXP];
__device__ int   g_tok[N_EXP * CAP];
__device__ float g_wgt[N_EXP * CAP];
// permuted+rounded A tiles: [e][mb][kt][4096 floats]  (fragment order)
__device__ float g_A1[(size_t)N_EXP * MB_MAX * KTILES * 4096];
__device__ float g_A2[(size_t)N_EXP * MB_MAX * KTILES * 4096];
// permuted+rounded weights: [e][nb(8)][kt][4096 floats]  (128-col blocks)
__device__ float g_W1p[(size_t)N_EXP * 8 * KTILES * 4096];
__device__ float g_W2p[(size_t)N_EXP * 8 * KTILES * 4096];

// ---------------- helpers ----------------
__device__ __forceinline__ uint32_t smem_u32(const void* p) {
    uint32_t a;
    asm("{ .reg .u64 t; cvta.to.shared.u64 t, %1; cvt.u32.u64 %0, t; }" : "=r"(a) : "l"(p));
    return a;
}
__device__ __forceinline__ unsigned f2tf32(float f) {
    unsigned r; asm("cvt.rna.tf32.f32 %0, %1;" : "=r"(r) : "f"(f)); return r;
}
__device__ __forceinline__ void mma_tf32(float* c, const uint32_t* a, const uint32_t* b) {
    asm volatile(
        "mma.sync.aligned.m16n8k8.row.col.f32.tf32.tf32.f32 "
        "{%0,%1,%2,%3}, {%4,%5,%6,%7}, {%8,%9}, {%0,%1,%2,%3};"
        : "+f"(c[0]), "+f"(c[1]), "+f"(c[2]), "+f"(c[3])
        : "r"(a[0]), "r"(a[1]), "r"(a[2]), "r"(a[3]),
          "r"(b[0]), "r"(b[1]));
}
#define CP_ASYNC16(dst, src) \
    asm volatile("cp.async.cg.shared.global [%0], [%1], 16;" :: "r"(dst), "l"(src))
#define CP_COMMIT()  asm volatile("cp.async.commit_group;" ::: "memory")
#define CP_WAIT1()   asm volatile("cp.async.wait_group 1;" ::: "memory")
#define LDS128(r, a) \
    asm volatile("ld.shared.v4.b32 {%0,%1,%2,%3}, [%4];" \
        : "=r"((r)[0]), "=r"((r)[1]), "=r"((r)[2]), "=r"((r)[3]) : "r"(a))
#define LDS64(r, a) \
    asm volatile("ld.shared.v2.b32 {%0,%1}, [%2];" \
        : "=r"((r)[0]), "=r"((r)[1]) : "r"(a))

// A fragment slot for element (r in 0..127, k in 0..31)
__device__ __forceinline__ int a_fidx(int r, int k) {
    return (((r >> 4) * 4 + (k >> 3)) << 7) + (((r & 7) * 4 + (k & 3)) << 2) +
           ((r >> 3) & 1) + 2 * ((k >> 2) & 1);
}
// B fragment slot for element (n in 0..127, k in 0..31)
__device__ __forceinline__ int b_fidx(int n, int k) {
    return (((n >> 3) * 4 + (k >> 3)) << 6) + (((n & 7) * 4 + (k & 3)) << 1) +
           ((k >> 2) & 1);
}

// ---------------- kernel: reset counters ----------------
__global__ void zero_cnt_kernel() {
    if (threadIdx.x < N_EXP) g_cnt[threadIdx.x] = 0;
}

// ---------------- kernel: gating + top-2 ----------------
__global__ void gate_kernel(const float* __restrict__ x,
                            const float* __restrict__ Wg,
                            const float* __restrict__ bg) {
    int tok  = blockIdx.x * 8 + (threadIdx.x >> 5);
    int lane = threadIdx.x & 31;
    if (tok >= N_TOK) return;
    const float* xr = x + (size_t)tok * D_MODEL;

    float s[8];
#pragma unroll
    for (int e = 0; e < 8; e++) s[e] = 0.f;
    for (int k = lane; k < D_MODEL; k += 32) {
        float xv = xr[k];
        const float4* wr = (const float4*)(Wg + (size_t)k * N_EXP);
        float4 w0 = wr[0], w1 = wr[1];
        s[0] += xv * w0.x; s[1] += xv * w0.y; s[2] += xv * w0.z; s[3] += xv * w0.w;
        s[4] += xv * w1.x; s[5] += xv * w1.y; s[6] += xv * w1.z; s[7] += xv * w1.w;
    }
#pragma unroll
    for (int e = 0; e < 8; e++)
#pragma unroll
        for (int off = 16; off > 0; off >>= 1)
            s[e] += __shfl_xor_sync(0xffffffffu, s[e], off);

    if (lane == 0) {
        float best = -3.4e38f, best2 = -3.4e38f;
        int e0 = 0, e1 = 0;
#pragma unroll
        for (int e = 0; e < 8; e++) {
            float v = s[e] + bg[e];
            if (v > best)       { best2 = best; e1 = e0; best = v; e0 = e; }
            else if (v > best2) { best2 = v; e1 = e; }
        }
        int p0 = atomicAdd(&g_cnt[e0], 1);
        g_tok[e0 * CAP + p0] = tok;
        g_wgt[e0 * CAP + p0] = best;
        int p1 = atomicAdd(&g_cnt[e1], 1);
        g_tok[e1 * CAP + p1] = tok;
        g_wgt[e1 * CAP + p1] = best2;
    }
}

// ---------------- kernel: weight permute+round ----------------
__global__ void w_perm_kernel(const float* __restrict__ W, int which) {
    __shared__ float stg[4096];
    float* dst = which ? g_W2p : g_W1p;
    const int kt = blockIdx.x, nb = blockIdx.y, e = blockIdx.z;
    const int tid = threadIdx.x;
    const int kr  = tid >> 3;
    const int nc8 = tid & 7;
    const float* Ws = W + (size_t)e * D_MODEL * D_MODEL;
#pragma unroll
    for (int i = 0; i < 4; i++) {
        int n_in = nc8 * 16 + i * 4;
        float4 v = *(const float4*)(Ws + (size_t)(kt * 32 + kr) * D_MODEL + nb * 128 + n_in);
        stg[b_fidx(n_in + 0, kr)] = __uint_as_float(f2tf32(v.x));
        stg[b_fidx(n_in + 1, kr)] = __uint_as_float(f2tf32(v.y));
        stg[b_fidx(n_in + 2, kr)] = __uint_as_float(f2tf32(v.z));
        stg[b_fidx(n_in + 3, kr)] = __uint_as_float(f2tf32(v.w));
    }
    __syncthreads();
    float4* d4 = (float4*)(dst + ((size_t)(e * 8 + nb) * KTILES + kt) * 4096);
    const float4* s4 = (const float4*)stg;
#pragma unroll
    for (int i = 0; i < 4; i++) d4[tid + i * 256] = s4[tid + i * 256];
}

// ---------------- kernel: gather + round + permute X -> g_A1 ----------------
__global__ void a1_perm_kernel(const float* __restrict__ x) {
    __shared__ float stg[4096];
    const int mb = blockIdx.x, e = blockIdx.y;
    const int cnt = g_cnt[e];
    if (mb * BM >= cnt) return;
    const int tid = threadIdx.x;
    const int r    = tid >> 1;
    const int half = tid & 1;
    int ai  = mb * BM + r;
    int tok = (ai < cnt) ? g_tok[e * CAP + ai] : g_tok[e * CAP];
    const float* src = x + (size_t)tok * D_MODEL;
    float* dstb = g_A1 + (size_t)(e * MB_MAX + mb) * KTILES * 4096;

    for (int kt = 0; kt < KTILES; kt++) {
#pragma unroll
        for (int i = 0; i < 4; i++) {
            int k_in = half * 16 + i * 4;
            float4 v = *(const float4*)(src + kt * 32 + k_in);
            stg[a_fidx(r, k_in + 0)] = __uint_as_float(f2tf32(v.x));
            stg[a_fidx(r, k_in + 1)] = __uint_as_float(f2tf32(v.y));
            stg[a_fidx(r, k_in + 2)] = __uint_as_float(f2tf32(v.z));
            stg[a_fidx(r, k_in + 3)] = __uint_as_float(f2tf32(v.w));
        }
        __syncthreads();
        float4* d4 = (float4*)(dstb + (size_t)kt * 4096);
        const float4* s4 = (const float4*)stg;
#pragma unroll
        for (int i = 0; i < 4; i++) d4[tid + i * 256] = s4[tid + i * 256];
        __syncthreads();
    }
}

// ---------------- kernel: grouped GEMM ----------------
// BM=128, BN=128, 128 threads, 4 warps (2m x 2n), warp tile 64x64.
// 3-stage cp.async ring (32KB/stage), one barrier per k-tile, 2 CTAs/SM.
// FIRST: D = relu(A1 @ W1^T + b1) -> g_A2 ; else: out[tok] += w*(A2 @ W2^T + b2)
template <bool FIRST>
__global__ void __launch_bounds__(NTHREADS, 2)
moe_gemm(const float* __restrict__ bias, float* __restrict__ out) {
    const int e   = blockIdx.z;
    const int cnt = g_cnt[e];
    const int mb  = blockIdx.y;
    if (mb * BM >= cnt) return;
    const int nb  = blockIdx.x;          // 0..7 (128-col block)

    extern __shared__ __align__(128) char smem[];
    const uint32_t sb = smem_u32(smem);
    const int tid  = threadIdx.x;
    const int lane = tid & 31;
    const int warp = tid >> 5;
    const int wm   = warp >> 1;          // 0..1 (64-row)
    const int wn   = warp & 1;           // 0..1 (64-col)
    const int g    = lane >> 2;
    const int tg   = lane & 3;

    const float* Asrc = (FIRST ? g_A1 : g_A2) + (size_t)(e * MB_MAX + mb) * KTILES * 4096;
    const float* Bsrc = (FIRST ? g_W1p : g_W2p) + (size_t)(e * 8 + nb) * KTILES * 4096;

    float c[32][4];
#pragma unroll
    for (int i = 0; i < 32; i++)
#pragma unroll
        for (int j = 0; j < 4; j++) c[i][j] = 0.f;

    // stage layout: [0,16K) A | [16K,32K) B
    auto load_stage = [&](int kt, int s) {
        uint32_t da = sb + s * STAGE_B + tid * 16;
        const float* sa = Asrc + (size_t)kt * 4096 + tid * 4;
        const float* sw = Bsrc + (size_t)kt * 4096 + tid * 4;
#pragma unroll
        for (int cc = 0; cc < 8; cc++) {
            CP_ASYNC16(da + cc * 2048,         sa + cc * 512);
            CP_ASYNC16(da + 16384 + cc * 2048, sw + cc * 512);
        }
    };

    load_stage(0, 0); CP_COMMIT();
    load_stage(1, 1); CP_COMMIT();

    const uint32_t aoff = wm * 8192 + lane * 16;           // A frag base
    const uint32_t boff = 16384 + wn * 8192 + lane * 8;    // B frag base

    for (int it = 0; it < KTILES; it++) {
        CP_WAIT1();
        __syncthreads();
        // stage (it+2)%3 == (it-1)%3: its reads finished before this barrier
        if (it + 2 < KTILES) load_stage(it + 2, (it + 2) % 3);
        CP_COMMIT();

        const uint32_t st = sb + (it % 3) * STAGE_B;
#pragma unroll
        for (int kk = 0; kk < 4; kk++) {
            uint32_t a[4][4], b[8][2];
#pragma unroll
            for (int mi = 0; mi < 4; mi++)
                LDS128(a[mi], st + aoff + mi * 2048 + kk * 512);
#pragma unroll
            for (int ni = 0; ni < 8; ni++)
                LDS64(b[ni], st + boff + ni * 1024 + kk * 256);
#pragma unroll
            for (int mi = 0; mi < 4; mi++)
#pragma unroll
                for (int ni = 0; ni < 8; ni++)
                    mma_tf32(c[mi * 8 + ni], a[mi], b[ni]);
        }
    }

    // ---- epilogue ----
    const float* brow = bias + e * D_MODEL;
#pragma unroll
    for (int mi = 0; mi < 4; mi++) {
#pragma unroll
        for (int ni = 0; ni < 8; ni++) {
#pragma unroll
            for (int j = 0; j < 4; j++) {
                int r_blk = wm * 64 + mi * 16 + g + 8 * (j >> 1);
                int grow  = mb * BM + r_blk;
                if (grow >= cnt) continue;
                int n_glob = nb * BN + wn * 64 + ni * 8 + 2 * tg + (j & 1);
                float v = c[mi * 8 + ni][j] + __ldg(brow + n_glob);
                if (FIRST) {
                    v = fmaxf(v, 0.f);
                    int kt = n_glob >> 5, k_in = n_glob & 31;
                    g_A2[((size_t)(e * MB_MAX + mb) * KTILES + kt) * 4096 +
                         a_fidx(r_blk, k_in)] = __uint_as_float(f2tf32(v));
                } else {
                    float w = g_wgt[e * CAP + grow];
                    atomicAdd(out + (size_t)g_tok[e * CAP + grow] * D_MODEL + n_glob,
                              v * w);
                }
            }
        }
    }
}

// ---------------- launch ----------------
extern "C" void kernel_launch(void* const* d_in, const int* in_sizes, int n_in,
                              void* d_out, int out_size) {
    const float* x  = (const float*)d_in[0];
    const float* Wg = (const float*)d_in[1];
    const float* bg = (const float*)d_in[2];
    const float* W1 = (const float*)d_in[3];
    const float* b1 = (const float*)d_in[4];
    const float* W2 = (const float*)d_in[5];
    const float* b2 = (const float*)d_in[6];
    float* out = (float*)d_out;

    cudaFuncSetAttribute(moe_gemm<true>,
                         cudaFuncAttributeMaxDynamicSharedMemorySize, SMEM_T);
    cudaFuncSetAttribute(moe_gemm<false>,
                         cudaFuncAttributeMaxDynamicSharedMemorySize, SMEM_T);

    cudaMemsetAsync(out, 0, (size_t)out_size * sizeof(float));
    zero_cnt_kernel<<<1, 32>>>();
    gate_kernel<<<N_TOK / 8, 256>>>(x, Wg, bg);

    dim3 wg(KTILES, 8, N_EXP);
    w_perm_kernel<<<wg, 256>>>(W1, 0);
    w_perm_kernel<<<wg, 256>>>(W2, 1);
    a1_perm_kernel<<<dim3(MB_MAX, N_EXP), 256>>>(x);

    dim3 grid(D_MODEL / BN, MB_MAX, N_EXP);   // (8, 64, 8)
    moe_gemm<true><<<grid, NTHREADS, SMEM_T>>>(b1, nullptr);
    moe_gemm<false><<<grid, NTHREADS, SMEM_T>>>(b2, out);
}

// round 10
// speedup vs baseline: 1.6908x; 1.4579x over previous
#include <cuda_runtime.h>
#include <cuda_fp16.h>
#include <cstdint>

#define D_MODEL 1024
#define N_EXP   8
#define N_TOK   8192
#define CAP     8192
#define MB_MAX  64
#define BM      128
#define BN      128
#define KTILES  32
#define NTHREADS 128
#define STAGE_B 16384         // 8KB A + 8KB B per stage
#define SMEM_T  (3 * STAGE_B) // 48 KB

// ---------------- device scratch ----------------
__device__ int    g_cnt[N_EXP];
__device__ int    g_tok[N_EXP * CAP];
__device__ float  g_wgt[N_EXP * CAP];
// fragment-permuted fp16 tiles: [e][mb][kt][4096 halves]
__device__ __half g_A1h[(size_t)N_EXP * MB_MAX * KTILES * 4096];
__device__ __half g_A2h[(size_t)N_EXP * MB_MAX * KTILES * 4096];
// fragment-permuted fp16 weights: [e][nb(8)][kt][4096 halves]
__device__ __half g_W1h[(size_t)N_EXP * 8 * KTILES * 4096];
__device__ __half g_W2h[(size_t)N_EXP * 8 * KTILES * 4096];

// ---------------- helpers ----------------
__device__ __forceinline__ uint32_t smem_u32(const void* p) {
    uint32_t a;
    asm("{ .reg .u64 t; cvta.to.shared.u64 t, %1; cvt.u32.u64 %0, t; }" : "=r"(a) : "l"(p));
    return a;
}
__device__ __forceinline__ void mma_f16(float* c, const uint32_t* a, const uint32_t* b) {
    asm volatile(
        "mma.sync.aligned.m16n8k16.row.col.f32.f16.f16.f32 "
        "{%0,%1,%2,%3}, {%4,%5,%6,%7}, {%8,%9}, {%0,%1,%2,%3};"
        : "+f"(c[0]), "+f"(c[1]), "+f"(c[2]), "+f"(c[3])
        : "r"(a[0]), "r"(a[1]), "r"(a[2]), "r"(a[3]),
          "r"(b[0]), "r"(b[1]));
}
#define CP_ASYNC16(dst, src) \
    asm volatile("cp.async.cg.shared.global [%0], [%1], 16;" :: "r"(dst), "l"(src))
#define CP_COMMIT()  asm volatile("cp.async.commit_group;" ::: "memory")
#define CP_WAIT1()   asm volatile("cp.async.wait_group 1;" ::: "memory")
#define LDS128(r, a) \
    asm volatile("ld.shared.v4.b32 {%0,%1,%2,%3}, [%4];" \
        : "=r"((r)[0]), "=r"((r)[1]), "=r"((r)[2]), "=r"((r)[3]) : "r"(a))
#define LDS64(r, a) \
    asm volatile("ld.shared.v2.b32 {%0,%1}, [%2];" \
        : "=r"((r)[0]), "=r"((r)[1]) : "r"(a))

// fp16 m16n8k16 fragment slots (indices in halves), r in 0..127, k in 0..31
// A block (16r x 16k) = 256 halves; thread=(r&7)*4+((k>>1)&3); reg=((r>>3)&1)+2*((k>>3)&1)
__device__ __forceinline__ int a_fidx16(int r, int k) {
    return (((r >> 4) * 2 + (k >> 4)) << 8) +
           (((r & 7) * 4 + ((k >> 1) & 3)) << 3) +
           ((((r >> 3) & 1) + 2 * ((k >> 3) & 1)) << 1) + (k & 1);
}
// B block (8n x 16k) = 128 halves; thread=(n&7)*4+((k>>1)&3); reg=(k>>3)&1
__device__ __forceinline__ int b_fidx16(int n, int k) {
    return (((n >> 3) * 2 + (k >> 4)) << 7) +
           (((n & 7) * 4 + ((k >> 1) & 3)) << 2) +
           (((k >> 3) & 1) << 1) + (k & 1);
}

// ---------------- kernel: reset counters ----------------
__global__ void zero_cnt_kernel() {
    if (threadIdx.x < N_EXP) g_cnt[threadIdx.x] = 0;
}

// ---------------- kernel: gating + top-2 ----------------
__global__ void gate_kernel(const float* __restrict__ x,
                            const float* __restrict__ Wg,
                            const float* __restrict__ bg) {
    int tok  = blockIdx.x * 8 + (threadIdx.x >> 5);
    int lane = threadIdx.x & 31;
    if (tok >= N_TOK) return;
    const float* xr = x + (size_t)tok * D_MODEL;

    float s[8];
#pragma unroll
    for (int e = 0; e < 8; e++) s[e] = 0.f;
    for (int k = lane; k < D_MODEL; k += 32) {
        float xv = xr[k];
        const float4* wr = (const float4*)(Wg + (size_t)k * N_EXP);
        float4 w0 = wr[0], w1 = wr[1];
        s[0] += xv * w0.x; s[1] += xv * w0.y; s[2] += xv * w0.z; s[3] += xv * w0.w;
        s[4] += xv * w1.x; s[5] += xv * w1.y; s[6] += xv * w1.z; s[7] += xv * w1.w;
    }
#pragma unroll
    for (int e = 0; e < 8; e++)
#pragma unroll
        for (int off = 16; off > 0; off >>= 1)
            s[e] += __shfl_xor_sync(0xffffffffu, s[e], off);

    if (lane == 0) {
        float best = -3.4e38f, best2 = -3.4e38f;
        int e0 = 0, e1 = 0;
#pragma unroll
        for (int e = 0; e < 8; e++) {
            float v = s[e] + bg[e];
            if (v > best)       { best2 = best; e1 = e0; best = v; e0 = e; }
            else if (v > best2) { best2 = v; e1 = e; }
        }
        int p0 = atomicAdd(&g_cnt[e0], 1);
        g_tok[e0 * CAP + p0] = tok;
        g_wgt[e0 * CAP + p0] = best;
        int p1 = atomicAdd(&g_cnt[e1], 1);
        g_tok[e1 * CAP + p1] = tok;
        g_wgt[e1 * CAP + p1] = best2;
    }
}

// ---------------- kernel: weight permute + fp16 convert ----------------
__global__ void w_perm_kernel(const float* __restrict__ W, int which) {
    __shared__ __half stg[4096];
    __half* dst = which ? g_W2h : g_W1h;
    const int kt = blockIdx.x, nb = blockIdx.y, e = blockIdx.z;
    const int tid = threadIdx.x;
    const int kr  = tid >> 3;          // k in tile 0..31
    const int nc8 = tid & 7;
    const float* Ws = W + (size_t)e * D_MODEL * D_MODEL;
#pragma unroll
    for (int i = 0; i < 4; i++) {
        int n_in = nc8 * 16 + i * 4;
        float4 v = *(const float4*)(Ws + (size_t)(kt * 32 + kr) * D_MODEL + nb * 128 + n_in);
        stg[b_fidx16(n_in + 0, kr)] = __float2half_rn(v.x);
        stg[b_fidx16(n_in + 1, kr)] = __float2half_rn(v.y);
        stg[b_fidx16(n_in + 2, kr)] = __float2half_rn(v.z);
        stg[b_fidx16(n_in + 3, kr)] = __float2half_rn(v.w);
    }
    __syncthreads();
    uint4* d4 = (uint4*)(dst + ((size_t)(e * 8 + nb) * KTILES + kt) * 4096);
    const uint4* s4 = (const uint4*)stg;
    d4[tid]       = s4[tid];
    d4[tid + 256] = s4[tid + 256];
}

// ---------------- kernel: gather + fp16 convert + permute X -> g_A1h ------
__global__ void a1_perm_kernel(const float* __restrict__ x) {
    __shared__ __half stg[4096];
    const int mb = blockIdx.x, e = blockIdx.y;
    const int cnt = g_cnt[e];
    if (mb * BM >= cnt) return;
    const int tid  = threadIdx.x;
    const int r    = tid >> 1;
    const int hlf  = tid & 1;
    int ai  = mb * BM + r;
    int tok = (ai < cnt) ? g_tok[e * CAP + ai] : g_tok[e * CAP];
    const float* src = x + (size_t)tok * D_MODEL;
    __half* dstb = g_A1h + (size_t)(e * MB_MAX + mb) * KTILES * 4096;

    for (int kt = 0; kt < KTILES; kt++) {
#pragma unroll
        for (int i = 0; i < 4; i++) {
            int k_in = hlf * 16 + i * 4;
            float4 v = *(const float4*)(src + kt * 32 + k_in);
            stg[a_fidx16(r, k_in + 0)] = __float2half_rn(v.x);
            stg[a_fidx16(r, k_in + 1)] = __float2half_rn(v.y);
            stg[a_fidx16(r, k_in + 2)] = __float2half_rn(v.z);
            stg[a_fidx16(r, k_in + 3)] = __float2half_rn(v.w);
        }
        __syncthreads();
        uint4* d4 = (uint4*)(dstb + (size_t)kt * 4096);
        const uint4* s4 = (const uint4*)stg;
        d4[tid]       = s4[tid];
        d4[tid + 256] = s4[tid + 256];
        __syncthreads();
    }
}

// ---------------- kernel: grouped GEMM (fp16 m16n8k16) ----------------
// BM=128, BN=128, 128 threads, 4 warps (2m x 2n), warp tile 64x64.
// 3-stage cp.async ring (16KB/stage), one barrier per k-tile, 2 CTAs/SM.
// FIRST: H = relu(A1 @ W1^T + b1) -> g_A2h ; else: out[tok] += w*(A2 @ W2^T + b2)
template <bool FIRST>
__global__ void __launch_bounds__(NTHREADS, 2)
moe_gemm(const float* __restrict__ bias, float* __restrict__ out) {
    const int e   = blockIdx.z;
    const int cnt = g_cnt[e];
    const int mb  = blockIdx.y;
    if (mb * BM >= cnt) return;
    const int nb  = blockIdx.x;

    extern __shared__ __align__(128) char smem[];
    const uint32_t sb = smem_u32(smem);
    const int tid  = threadIdx.x;
    const int lane = tid & 31;
    const int warp = tid >> 5;
    const int wm   = warp >> 1;          // 0..1 (64-row)
    const int wn   = warp & 1;           // 0..1 (64-col)
    const int g    = lane >> 2;
    const int tg   = lane & 3;

    const __half* Asrc = (FIRST ? g_A1h : g_A2h) + (size_t)(e * MB_MAX + mb) * KTILES * 4096;
    const __half* Bsrc = (FIRST ? g_W1h : g_W2h) + (size_t)(e * 8 + nb) * KTILES * 4096;

    float c[32][4];
#pragma unroll
    for (int i = 0; i < 32; i++)
#pragma unroll
        for (int j = 0; j < 4; j++) c[i][j] = 0.f;

    // stage layout: [0,8K) A | [8K,16K) B
    auto load_stage = [&](int kt, int s) {
        uint32_t da = sb + s * STAGE_B + tid * 16;
        const char* sa = (const char*)(Asrc + (size_t)kt * 4096) + tid * 16;
        const char* sw = (const char*)(Bsrc + (size_t)kt * 4096) + tid * 16;
#pragma unroll
        for (int cc = 0; cc < 4; cc++) {
            CP_ASYNC16(da + cc * 2048,        sa + cc * 2048);
            CP_ASYNC16(da + 8192 + cc * 2048, sw + cc * 2048);
        }
    };

    load_stage(0, 0); CP_COMMIT();
    load_stage(1, 1); CP_COMMIT();

    const uint32_t aoff = wm * 4096 + lane * 16;          // A frag base (bytes)
    const uint32_t boff = 8192 + wn * 4096 + lane * 8;    // B frag base (bytes)

    for (int it = 0; it < KTILES; it++) {
        CP_WAIT1();
        __syncthreads();
        // stage (it+2)%3 == (it-1)%3: reads finished before this barrier
        if (it + 2 < KTILES) load_stage(it + 2, (it + 2) % 3);
        CP_COMMIT();

        const uint32_t st = sb + (it % 3) * STAGE_B;
#pragma unroll
        for (int kk = 0; kk < 2; kk++) {
            uint32_t a[4][4], b[8][2];
#pragma unroll
            for (int mi = 0; mi < 4; mi++)
                LDS128(a[mi], st + aoff + mi * 1024 + kk * 512);
#pragma unroll
            for (int ni = 0; ni < 8; ni++)
                LDS64(b[ni], st + boff + ni * 512 + kk * 256);
#pragma unroll
            for (int mi = 0; mi < 4; mi++)
#pragma unroll
                for (int ni = 0; ni < 8; ni++)
                    mma_f16(c[mi * 8 + ni], a[mi], b[ni]);
        }
    }

    // ---- epilogue ----
    const float* brow = bias + e * D_MODEL;
#pragma unroll
    for (int mi = 0; mi < 4; mi++) {
#pragma unroll
        for (int ni = 0; ni < 8; ni++) {
#pragma unroll
            for (int j = 0; j < 4; j++) {
                int r_blk = wm * 64 + mi * 16 + g + 8 * (j >> 1);
                int grow  = mb * BM + r_blk;
                if (grow >= cnt) continue;
                int n_glob = nb * BN + wn * 64 + ni * 8 + 2 * tg + (j & 1);
                float v = c[mi * 8 + ni][j] + __ldg(brow + n_glob);
                if (FIRST) {
                    v = fmaxf(v, 0.f);
                    int kt = n_glob >> 5, k_in = n_glob & 31;
                    g_A2h[((size_t)(e * MB_MAX + mb) * KTILES + kt) * 4096 +
                          a_fidx16(r_blk, k_in)] = __float2half_rn(v);
                } else {
                    float w = g_wgt[e * CAP + grow];
                    atomicAdd(out + (size_t)g_tok[e * CAP + grow] * D_MODEL + n_glob,
                              v * w);
                }
            }
        }
    }
}

// ---------------- launch ----------------
extern "C" void kernel_launch(void* const* d_in, const int* in_sizes, int n_in,
                              void* d_out, int out_size) {
    const float* x  = (const float*)d_in[0];
    const float* Wg = (const float*)d_in[1];
    const float* bg = (const float*)d_in[2];
    const float* W1 = (const float*)d_in[3];
    const float* b1 = (const float*)d_in[4];
    const float* W2 = (const float*)d_in[5];
    const float* b2 = (const float*)d_in[6];
    float* out = (float*)d_out;

    cudaFuncSetAttribute(moe_gemm<true>,
                         cudaFuncAttributeMaxDynamicSharedMemorySize, SMEM_T);
    cudaFuncSetAttribute(moe_gemm<false>,
                         cudaFuncAttributeMaxDynamicSharedMemorySize, SMEM_T);

    cudaMemsetAsync(out, 0, (size_t)out_size * sizeof(float));
    zero_cnt_kernel<<<1, 32>>>();
    gate_kernel<<<N_TOK / 8, 256>>>(x, Wg, bg);

    dim3 wg(KTILES, 8, N_EXP);
    w_perm_kernel<<<wg, 256>>>(W1, 0);
    w_perm_kernel<<<wg, 256>>>(W2, 1);
    a1_perm_kernel<<<dim3(MB_MAX, N_EXP), 256>>>(x);

    dim3 grid(D_MODEL / BN, MB_MAX, N_EXP);   // (8, 64, 8)
    moe_gemm<true><<<grid, NTHREADS, SMEM_T>>>(b1, nullptr);
    moe_gemm<false><<<grid, NTHREADS, SMEM_T>>>(b2, out);
}